// round 15
// baseline (speedup 1.0000x reference)
#include <cuda_runtime.h>
#include <cstdint>

#define N 384
#define C 64
#define W_COLS 512
#define THREADS 256
#define NWARP 8
#define NI 64             // i-rows per CTA
#define KCH 32            // k-chunk per stage
#define NCHUNK (N / KCH)  // 12
#define AS_LD 388         // fp32 words per B row (conflict-free fragment LDS)
#define Q_LD 68           // Q' smem row stride (conflict-free fold)
#define NBUF 3

// ---------------- scratch ----------------
__device__ float g_W[N * W_COLS];        // x @ w_w^T  [384][512]
__device__ float g_P[N * N];             // exp(AB)  [i][j]
__device__ float g_QT[N * N];            // exp(CD) transposed: QT[k][i]
__device__ float g_RT[N * N];            // exp(EF) transposed, tf32-rounded: RT[k][j]
__device__ float g_num[N * C];
__device__ float g_den[N];

__device__ __forceinline__ float to_tf32(float x) {
    float r;
    asm("cvt.rna.tf32.f32 %0, %1;" : "=f"(r) : "f"(x));
    return r;
}
__device__ __forceinline__ void cp16(uint32_t dst, const void* src) {
    asm volatile("cp.async.cg.shared.global [%0], [%1], 16;" :: "r"(dst), "l"(src));
}

// ---------------- K1: W = x @ w_w^T, smem-tiled 32x32 ----------------
__global__ void k_gemm_w(const float* __restrict__ x, const float* __restrict__ ww) {
    __shared__ float xs[32][67], ws[32][67];
    int o0 = blockIdx.x * 32, n0 = blockIdx.y * 32;
    int tx = threadIdx.x, ty = threadIdx.y;
    int t = ty * 16 + tx;
    for (int q = t; q < 32 * 64; q += 256) {
        int rr = q >> 6, cc = q & 63;
        xs[rr][cc] = x[(n0 + rr) * C + cc];
        ws[rr][cc] = ww[(o0 + rr) * C + cc];
    }
    __syncthreads();
    float s00 = 0.f, s01 = 0.f, s10 = 0.f, s11 = 0.f;
#pragma unroll
    for (int c = 0; c < 64; ++c) {
        float u0 = xs[2 * ty][c], u1 = xs[2 * ty + 1][c];
        float v0 = ws[2 * tx][c], v1 = ws[2 * tx + 1][c];
        s00 += u0 * v0; s01 += u0 * v1;
        s10 += u1 * v0; s11 += u1 * v1;
    }
    int n = n0 + 2 * ty, o = o0 + 2 * tx;
    g_W[n * W_COLS + o] = s00;       g_W[n * W_COLS + o + 1] = s01;
    g_W[(n + 1) * W_COLS + o] = s10; g_W[(n + 1) * W_COLS + o + 1] = s11;
}

// ---------------- K2: fused scores + exp (+transposes), 32x32 tiles ----------------
// No max-shift: scores are O(1) (w scaled 0.05); any per-matrix shift cancels in num/den.
__global__ void k_pqr() {
    __shared__ float us[32][67], vs[32][67];
    int z = blockIdx.z;
    int r0 = blockIdx.y * 32, c0 = blockIdx.x * 32;
    int tx = threadIdx.x, ty = threadIdx.y;
    int t = ty * 16 + tx;
    int up = (z == 0) ? 0 : (z == 1) ? 3 : 5;
    int vp = (z == 0) ? 1 : (z == 1) ? 2 : 4;
    for (int q = t; q < 32 * 64; q += 256) {
        int rr = q >> 6, cc = q & 63;
        us[rr][cc] = g_W[(r0 + rr) * W_COLS + up * C + cc];
        vs[rr][cc] = g_W[(c0 + rr) * W_COLS + vp * C + cc];
    }
    __syncthreads();
    float s00 = 0.f, s01 = 0.f, s10 = 0.f, s11 = 0.f;
#pragma unroll
    for (int c = 0; c < 64; ++c) {
        float u0 = us[2 * ty][c], u1 = us[2 * ty + 1][c];
        float v0 = vs[2 * tx][c], v1 = vs[2 * tx + 1][c];
        s00 += u0 * v0; s01 += u0 * v1;
        s10 += u1 * v0; s11 += u1 * v1;
    }
    s00 = __expf(s00 * 0.125f);
    s01 = __expf(s01 * 0.125f);
    s10 = __expf(s10 * 0.125f);
    s11 = __expf(s11 * 0.125f);
    int row = r0 + 2 * ty, col = c0 + 2 * tx;
    if (z == 0) {
        g_P[row * N + col] = s00;       g_P[row * N + col + 1] = s01;
        g_P[(row + 1) * N + col] = s10; g_P[(row + 1) * N + col + 1] = s11;
    } else if (z == 1) {
        g_QT[row * N + col] = s00;       g_QT[row * N + col + 1] = s01;
        g_QT[(row + 1) * N + col] = s10; g_QT[(row + 1) * N + col + 1] = s11;
    } else {
        g_RT[row * N + col] = to_tf32(s00);       g_RT[row * N + col + 1] = to_tf32(s01);
        g_RT[(row + 1) * N + col] = to_tf32(s10); g_RT[(row + 1) * N + col + 1] = to_tf32(s11);
    }
}

// ---------------- K3: tf32 HMMA main contraction (R10 base + premultiplied Q') ----------------
// grid = (65, 6): blockIdx.x = d (64 => denominator), blockIdx.y = i-tile (64 rows)
#define B_BYTES (KCH * AS_LD * 4)                  // 49664
#define Q_BYTES (KCH * Q_LD * 4)                   // 8704
#define OFF_B   0
#define OFF_QT  (NBUF * B_BYTES)                   // 148992
#define OFF_V1  (OFF_QT + NBUF * Q_BYTES)          // 175104
#define OFF_V2  (OFF_V1 + N * 4)
#define OFF_PP  (OFF_V2 + N * 4)
#define SMEM_BYTES (OFF_PP + NWARP * NI * 4)       // 180224

__device__ __forceinline__ void mma_tf32(float* c, const uint32_t* a, const uint32_t* b) {
    asm("mma.sync.aligned.m16n8k8.row.col.f32.tf32.tf32.f32 "
        "{%0,%1,%2,%3}, {%4,%5,%6,%7}, {%8,%9}, {%0,%1,%2,%3};"
        : "+f"(c[0]), "+f"(c[1]), "+f"(c[2]), "+f"(c[3])
        : "r"(a[0]), "r"(a[1]), "r"(a[2]), "r"(a[3]), "r"(b[0]), "r"(b[1]));
}

__global__ __launch_bounds__(THREADS, 1) void k_main() {
    extern __shared__ char smc[];
    float* v1s = (float*)(smc + OFF_V1);
    float* v2s = (float*)(smc + OFF_V2);
    float* pp  = (float*)(smc + OFF_PP);

    int d = blockIdx.x;
    int i0 = blockIdx.y * NI;
    int t = threadIdx.x;
    int w = t >> 5, lane = t & 31;
    int g = lane >> 2, tg = lane & 3;
    int j0w = w * 48;

    uint32_t smb = (uint32_t)__cvta_generic_to_shared(smc);

    // v1/v2 first: Q' staging needs v2s
    if (d < C) {
        for (int j = t; j < N; j += THREADS) {
            v1s[j] = g_W[j * W_COLS + 6 * C + d];
            v2s[j] = g_W[j * W_COLS + 7 * C + d];
        }
    } else {
        for (int j = t; j < N; j += THREADS) { v1s[j] = 1.f; v2s[j] = 1.f; }
    }
    __syncthreads();

    // Stage chunks 0 and 1: B via cp.async; Q' = QT * v2 via LDG+FMUL+STS
#pragma unroll
    for (int pc = 0; pc < 2; ++pc) {
        uint32_t bo = OFF_B + (uint32_t)pc * B_BYTES;
        float* Qs = (float*)(smc + OFF_QT + pc * Q_BYTES);
        int k0 = pc * KCH;
        for (int q = t; q < KCH * (N / 4); q += THREADS) {
            int r = q / (N / 4), u = q - r * (N / 4);
            cp16(smb + bo + (uint32_t)(r * AS_LD + u * 4) * 4u, &g_RT[(k0 + r) * N + u * 4]);
        }
        asm volatile("cp.async.commit_group;" ::: "memory");
        for (int q = t; q < KCH * (NI / 4); q += THREADS) {
            int r = q >> 4, u = q & 15;
            float4 v = *(const float4*)&g_QT[(k0 + r) * N + i0 + u * 4];
            float sc = v2s[k0 + r];
            v.x *= sc; v.y *= sc; v.z *= sc; v.w *= sc;
            *(float4*)&Qs[r * Q_LD + u * 4] = v;
        }
    }

    // Hoist A fragments into registers: chunk-invariant, built from g_P * v1
    uint32_t a[4][6][4];
#pragma unroll
    for (int mt = 0; mt < 4; ++mt)
#pragma unroll
        for (int js = 0; js < 6; ++js) {
            int i = i0 + mt * 16 + g;
            int j = j0w + js * 8 + tg;
            float v1a = v1s[j], v1b = v1s[j + 4];
            a[mt][js][0] = __float_as_uint(to_tf32(g_P[i * N + j] * v1a));
            a[mt][js][1] = __float_as_uint(to_tf32(g_P[(i + 8) * N + j] * v1a));
            a[mt][js][2] = __float_as_uint(to_tf32(g_P[i * N + j + 4] * v1b));
            a[mt][js][3] = __float_as_uint(to_tf32(g_P[(i + 8) * N + j + 4] * v1b));
        }

    float numacc[8];
#pragma unroll
    for (int s = 0; s < 8; ++s) numacc[s] = 0.f;

    for (int ch = 0; ch < NCHUNK; ++ch) {
        if (ch + 2 < NCHUNK) {
            uint32_t bo = OFF_B + (uint32_t)((ch + 2) % NBUF) * B_BYTES;
            float* Qs = (float*)(smc + OFF_QT + ((ch + 2) % NBUF) * Q_BYTES);
            int k0 = (ch + 2) * KCH;
            for (int q = t; q < KCH * (N / 4); q += THREADS) {
                int r = q / (N / 4), u = q - r * (N / 4);
                cp16(smb + bo + (uint32_t)(r * AS_LD + u * 4) * 4u, &g_RT[(k0 + r) * N + u * 4]);
            }
            asm volatile("cp.async.commit_group;" ::: "memory");
            for (int q = t; q < KCH * (NI / 4); q += THREADS) {
                int r = q >> 4, u = q & 15;
                float4 v = *(const float4*)&g_QT[(k0 + r) * N + i0 + u * 4];
                float sc = v2s[k0 + r];
                v.x *= sc; v.y *= sc; v.z *= sc; v.w *= sc;
                *(float4*)&Qs[r * Q_LD + u * 4] = v;
            }
            asm volatile("cp.async.wait_group 2;" ::: "memory");
        } else if (ch + 2 == NCHUNK) {
            asm volatile("cp.async.wait_group 1;" ::: "memory");
        } else {
            asm volatile("cp.async.wait_group 0;" ::: "memory");
        }
        __syncthreads();

        const float* Bb = (const float*)(smc + OFF_B + (ch % NBUF) * B_BYTES);
        const float* Qb = (const float*)(smc + OFF_QT + (ch % NBUF) * Q_BYTES);

#pragma unroll
        for (int half = 0; half < 2; ++half) {
            float acc[4][2][4];
#pragma unroll
            for (int mt = 0; mt < 4; ++mt)
#pragma unroll
                for (int nt = 0; nt < 2; ++nt)
#pragma unroll
                    for (int r = 0; r < 4; ++r) acc[mt][nt][r] = 0.f;

#pragma unroll
            for (int js = 0; js < 6; ++js) {
                int j0 = j0w + js * 8;
                uint32_t b[2][2];
#pragma unroll
                for (int nt = 0; nt < 2; ++nt) {
                    const uint32_t* bp =
                        (const uint32_t*)(Bb + (half * 16 + nt * 8 + g) * AS_LD + j0 + tg);
                    b[nt][0] = bp[0];
                    b[nt][1] = bp[4];
                }
#pragma unroll
                for (int mt = 0; mt < 4; ++mt)
#pragma unroll
                    for (int nt = 0; nt < 2; ++nt)
                        mma_tf32(acc[mt][nt], a[mt][js], b[nt]);
            }

            // Fold: numacc += G * Q'[k][i]   (v2 already folded into Q')
#pragma unroll
            for (int nt = 0; nt < 2; ++nt) {
                int kk0 = half * 16 + nt * 8 + 2 * tg;
#pragma unroll
                for (int mt = 0; mt < 4; ++mt)
#pragma unroll
                    for (int r = 0; r < 4; ++r) {
                        int kk = kk0 + (r & 1);
                        int iloc = mt * 16 + ((r >> 1) << 3) + g;
                        numacc[mt * 2 + (r >> 1)] +=
                            acc[mt][nt][r] * Qb[kk * Q_LD + iloc];
                    }
            }
        }
        __syncthreads();  // all warps done reading this buffer before it's re-staged
    }

    // Reduce over quad lanes (tg), then across 8 warps via smem
#pragma unroll
    for (int s = 0; s < 8; ++s) {
        float v = numacc[s];
        v += __shfl_xor_sync(0xffffffffu, v, 1);
        v += __shfl_xor_sync(0xffffffffu, v, 2);
        if (tg == 0) {
            int iloc = (s >> 1) * 16 + (s & 1) * 8 + g;
            pp[w * NI + iloc] = v;
        }
    }
    __syncthreads();
    if (t < NI) {
        float tot = 0.f;
#pragma unroll
        for (int q = 0; q < NWARP; ++q) tot += pp[q * NI + t];
        int gi = i0 + t;
        if (d < C) g_num[gi * C + d] = tot;
        else       g_den[gi] = tot;
    }
}

// ---------------- K4: out = num / den ----------------
__global__ void k_final(float* __restrict__ out) {
    int idx = blockIdx.x * blockDim.x + threadIdx.x;
    if (idx >= N * C) return;
    int i = idx / C;
    out[idx] = g_num[idx] / g_den[i];
}

// ---------------- launcher ----------------
extern "C" void kernel_launch(void* const* d_in, const int* in_sizes, int n_in,
                              void* d_out, int out_size) {
    const float* x  = (const float*)d_in[0];
    const float* ww = (const float*)d_in[1];
    if (n_in >= 2 && in_sizes[0] == 8 * C * C && in_sizes[1] == N * C) {
        const float* tmp = x; x = ww; ww = tmp;
    }
    float* out = (float*)d_out;

    cudaFuncSetAttribute(k_main, cudaFuncAttributeMaxDynamicSharedMemorySize, SMEM_BYTES);

    dim3 g1(W_COLS / 32, N / 32);
    k_gemm_w<<<g1, dim3(16, 16)>>>(x, ww);
    dim3 g2(N / 32, N / 32, 3);
    k_pqr<<<g2, dim3(16, 16)>>>();
    dim3 g3(C + 1, N / NI);
    k_main<<<g3, THREADS, SMEM_BYTES>>>();
    k_final<<<(N * C + 255) / 256, 256>>>(out);
}

// round 16
// speedup vs baseline: 1.1315x; 1.1315x over previous
#include <cuda_runtime.h>
#include <cstdint>

#define N 384
#define C 64
#define W_COLS 512
#define THREADS 256
#define NWARP 8
#define NI 64             // i-rows per CTA
#define KCH 32            // k-chunk per stage
#define NCHUNK (N / KCH)  // 12
#define AS_LD 388         // fp32 words per B row (conflict-free fragment LDS)
#define Q_LD 68           // QT smem row stride (conflict-free fold)
#define NBUF 3

// ---------------- scratch ----------------
__device__ float g_W[N * W_COLS];        // x @ w_w^T  [384][512]
__device__ float g_P[N * N];             // exp(AB)  [i][j]
__device__ float g_QT[N * N];            // exp(CD) transposed: QT[k][i]
__device__ float g_RT[N * N];            // exp(EF) transposed, tf32-rounded: RT[k][j]
__device__ float g_num[N * C];
__device__ float g_den[N];

__device__ __forceinline__ float to_tf32(float x) {
    float r;
    asm("cvt.rna.tf32.f32 %0, %1;" : "=f"(r) : "f"(x));
    return r;
}
__device__ __forceinline__ void cp16(uint32_t dst, const void* src) {
    asm volatile("cp.async.cg.shared.global [%0], [%1], 16;" :: "r"(dst), "l"(src));
}

// ---------------- K1: W = x @ w_w^T, smem-tiled 32x32 (measured 8.5us) ----------------
__global__ void k_gemm_w(const float* __restrict__ x, const float* __restrict__ ww) {
    __shared__ float xs[32][67], ws[32][67];
    int o0 = blockIdx.x * 32, n0 = blockIdx.y * 32;
    int tx = threadIdx.x, ty = threadIdx.y;
    int t = ty * 16 + tx;
    for (int q = t; q < 32 * 64; q += 256) {
        int rr = q >> 6, cc = q & 63;
        xs[rr][cc] = x[(n0 + rr) * C + cc];
        ws[rr][cc] = ww[(o0 + rr) * C + cc];
    }
    __syncthreads();
    float s00 = 0.f, s01 = 0.f, s10 = 0.f, s11 = 0.f;
#pragma unroll
    for (int c = 0; c < 64; ++c) {
        float u0 = xs[2 * ty][c], u1 = xs[2 * ty + 1][c];
        float v0 = ws[2 * tx][c], v1 = ws[2 * tx + 1][c];
        s00 += u0 * v0; s01 += u0 * v1;
        s10 += u1 * v0; s11 += u1 * v1;
    }
    int n = n0 + 2 * ty, o = o0 + 2 * tx;
    g_W[n * W_COLS + o] = s00;       g_W[n * W_COLS + o + 1] = s01;
    g_W[(n + 1) * W_COLS + o] = s10; g_W[(n + 1) * W_COLS + o + 1] = s11;
}

// ---------------- K2: fused scores + exp (+transposes), 64x64 tiles ----------------
// No max-shift: scores are O(1) (w scaled 0.05); any per-matrix shift cancels in num/den.
// Thread (ty,tx) computes rows ty+16r, cols tx+16s (r,s in 0..3).
__global__ void k_pqr() {
    __shared__ float us[64][65], vs[64][65];
    int z = blockIdx.z;
    int r0 = blockIdx.y * 64, c0 = blockIdx.x * 64;
    int tx = threadIdx.x, ty = threadIdx.y;
    int t = ty * 16 + tx;
    int up = (z == 0) ? 0 : (z == 1) ? 3 : 5;
    int vp = (z == 0) ? 1 : (z == 1) ? 2 : 4;
    for (int q = t; q < 64 * 64; q += 256) {
        int rr = q >> 6, cc = q & 63;
        us[rr][cc] = g_W[(r0 + rr) * W_COLS + up * C + cc];
        vs[rr][cc] = g_W[(c0 + rr) * W_COLS + vp * C + cc];
    }
    __syncthreads();
    float acc[4][4];
#pragma unroll
    for (int r = 0; r < 4; ++r)
#pragma unroll
        for (int s = 0; s < 4; ++s) acc[r][s] = 0.f;
#pragma unroll 8
    for (int c = 0; c < 64; ++c) {
        float u[4], v[4];
#pragma unroll
        for (int r = 0; r < 4; ++r) u[r] = us[ty + 16 * r][c];
#pragma unroll
        for (int s = 0; s < 4; ++s) v[s] = vs[tx + 16 * s][c];
#pragma unroll
        for (int r = 0; r < 4; ++r)
#pragma unroll
            for (int s = 0; s < 4; ++s) acc[r][s] += u[r] * v[s];
    }
#pragma unroll
    for (int r = 0; r < 4; ++r) {
        int row = r0 + ty + 16 * r;
#pragma unroll
        for (int s = 0; s < 4; ++s) {
            int col = c0 + tx + 16 * s;
            float e = __expf(acc[r][s] * 0.125f);
            if (z == 0)      g_P[row * N + col]  = e;
            else if (z == 1) g_QT[row * N + col] = e;
            else             g_RT[row * N + col] = to_tf32(e);
        }
    }
}

// ---------------- K3: tf32 HMMA main contraction (byte-exact R10) ----------------
// grid = (65, 6): blockIdx.x = d (64 => denominator), blockIdx.y = i-tile (64 rows)
#define B_BYTES (KCH * AS_LD * 4)                  // 49664
#define Q_BYTES (KCH * Q_LD * 4)                   // 8704
#define OFF_B   0
#define OFF_QT  (NBUF * B_BYTES)                   // 148992
#define OFF_V1  (OFF_QT + NBUF * Q_BYTES)          // 175104
#define OFF_V2  (OFF_V1 + N * 4)
#define OFF_PP  (OFF_V2 + N * 4)
#define SMEM_BYTES (OFF_PP + NWARP * NI * 4)       // 180224

__device__ __forceinline__ void mma_tf32(float* c, const uint32_t* a, const uint32_t* b) {
    asm("mma.sync.aligned.m16n8k8.row.col.f32.tf32.tf32.f32 "
        "{%0,%1,%2,%3}, {%4,%5,%6,%7}, {%8,%9}, {%0,%1,%2,%3};"
        : "+f"(c[0]), "+f"(c[1]), "+f"(c[2]), "+f"(c[3])
        : "r"(a[0]), "r"(a[1]), "r"(a[2]), "r"(a[3]), "r"(b[0]), "r"(b[1]));
}

__global__ __launch_bounds__(THREADS, 1) void k_main() {
    extern __shared__ char smc[];
    float* v1s = (float*)(smc + OFF_V1);
    float* v2s = (float*)(smc + OFF_V2);
    float* pp  = (float*)(smc + OFF_PP);

    int d = blockIdx.x;
    int i0 = blockIdx.y * NI;
    int t = threadIdx.x;
    int w = t >> 5, lane = t & 31;
    int g = lane >> 2, tg = lane & 3;
    int j0w = w * 48;

    uint32_t smb = (uint32_t)__cvta_generic_to_shared(smc);

    // Stage chunks 0 and 1
#pragma unroll
    for (int pc = 0; pc < 2; ++pc) {
        uint32_t bo = OFF_B + (uint32_t)pc * B_BYTES;
        uint32_t qo = OFF_QT + (uint32_t)pc * Q_BYTES;
        int k0 = pc * KCH;
        for (int q = t; q < KCH * (N / 4); q += THREADS) {
            int r = q / (N / 4), u = q - r * (N / 4);
            cp16(smb + bo + (uint32_t)(r * AS_LD + u * 4) * 4u, &g_RT[(k0 + r) * N + u * 4]);
        }
        for (int q = t; q < KCH * (NI / 4); q += THREADS) {
            int r = q / (NI / 4), u = q - r * (NI / 4);
            cp16(smb + qo + (uint32_t)(r * Q_LD + u * 4) * 4u, &g_QT[(k0 + r) * N + i0 + u * 4]);
        }
        asm volatile("cp.async.commit_group;" ::: "memory");
    }

    if (d < C) {
        for (int j = t; j < N; j += THREADS) {
            v1s[j] = g_W[j * W_COLS + 6 * C + d];
            v2s[j] = g_W[j * W_COLS + 7 * C + d];
        }
    } else {
        for (int j = t; j < N; j += THREADS) { v1s[j] = 1.f; v2s[j] = 1.f; }
    }
    __syncthreads();

    // Hoist A fragments into registers: chunk-invariant, built from g_P * v1
    uint32_t a[4][6][4];
#pragma unroll
    for (int mt = 0; mt < 4; ++mt)
#pragma unroll
        for (int js = 0; js < 6; ++js) {
            int i = i0 + mt * 16 + g;
            int j = j0w + js * 8 + tg;
            float v1a = v1s[j], v1b = v1s[j + 4];
            a[mt][js][0] = __float_as_uint(to_tf32(g_P[i * N + j] * v1a));
            a[mt][js][1] = __float_as_uint(to_tf32(g_P[(i + 8) * N + j] * v1a));
            a[mt][js][2] = __float_as_uint(to_tf32(g_P[i * N + j + 4] * v1b));
            a[mt][js][3] = __float_as_uint(to_tf32(g_P[(i + 8) * N + j + 4] * v1b));
        }

    float numacc[8];
#pragma unroll
    for (int s = 0; s < 8; ++s) numacc[s] = 0.f;

    for (int ch = 0; ch < NCHUNK; ++ch) {
        if (ch + 2 < NCHUNK) {
            uint32_t bo = OFF_B + (uint32_t)((ch + 2) % NBUF) * B_BYTES;
            uint32_t qo = OFF_QT + (uint32_t)((ch + 2) % NBUF) * Q_BYTES;
            int k0 = (ch + 2) * KCH;
            for (int q = t; q < KCH * (N / 4); q += THREADS) {
                int r = q / (N / 4), u = q - r * (N / 4);
                cp16(smb + bo + (uint32_t)(r * AS_LD + u * 4) * 4u, &g_RT[(k0 + r) * N + u * 4]);
            }
            for (int q = t; q < KCH * (NI / 4); q += THREADS) {
                int r = q / (NI / 4), u = q - r * (NI / 4);
                cp16(smb + qo + (uint32_t)(r * Q_LD + u * 4) * 4u, &g_QT[(k0 + r) * N + i0 + u * 4]);
            }
            asm volatile("cp.async.commit_group;" ::: "memory");
            asm volatile("cp.async.wait_group 2;" ::: "memory");
        } else if (ch + 2 == NCHUNK) {
            asm volatile("cp.async.wait_group 1;" ::: "memory");
        } else {
            asm volatile("cp.async.wait_group 0;" ::: "memory");
        }
        __syncthreads();

        const float* Bb = (const float*)(smc + OFF_B + (ch % NBUF) * B_BYTES);
        const float* Qb = (const float*)(smc + OFF_QT + (ch % NBUF) * Q_BYTES);

#pragma unroll
        for (int half = 0; half < 2; ++half) {
            float acc[4][2][4];
#pragma unroll
            for (int mt = 0; mt < 4; ++mt)
#pragma unroll
                for (int nt = 0; nt < 2; ++nt)
#pragma unroll
                    for (int r = 0; r < 4; ++r) acc[mt][nt][r] = 0.f;

#pragma unroll
            for (int js = 0; js < 6; ++js) {
                int j0 = j0w + js * 8;
                uint32_t b[2][2];
#pragma unroll
                for (int nt = 0; nt < 2; ++nt) {
                    const uint32_t* bp =
                        (const uint32_t*)(Bb + (half * 16 + nt * 8 + g) * AS_LD + j0 + tg);
                    b[nt][0] = bp[0];
                    b[nt][1] = bp[4];
                }
#pragma unroll
                for (int mt = 0; mt < 4; ++mt)
#pragma unroll
                    for (int nt = 0; nt < 2; ++nt)
                        mma_tf32(acc[mt][nt], a[mt][js], b[nt]);
            }

            // Fold: numacc += G * QT[k][i] * v2[k]
#pragma unroll
            for (int nt = 0; nt < 2; ++nt) {
                int kk0 = half * 16 + nt * 8 + 2 * tg;
                float v2a = v2s[ch * KCH + kk0];
                float v2b = v2s[ch * KCH + kk0 + 1];
#pragma unroll
                for (int mt = 0; mt < 4; ++mt)
#pragma unroll
                    for (int r = 0; r < 4; ++r) {
                        int kk = kk0 + (r & 1);
                        int iloc = mt * 16 + ((r >> 1) << 3) + g;
                        numacc[mt * 2 + (r >> 1)] +=
                            acc[mt][nt][r] * Qb[kk * Q_LD + iloc] * ((r & 1) ? v2b : v2a);
                    }
            }
        }
        __syncthreads();  // all warps done reading this buffer before it's re-staged
    }

    // Reduce over quad lanes (tg), then across 8 warps via smem
#pragma unroll
    for (int s = 0; s < 8; ++s) {
        float v = numacc[s];
        v += __shfl_xor_sync(0xffffffffu, v, 1);
        v += __shfl_xor_sync(0xffffffffu, v, 2);
        if (tg == 0) {
            int iloc = (s >> 1) * 16 + (s & 1) * 8 + g;
            pp[w * NI + iloc] = v;
        }
    }
    __syncthreads();
    if (t < NI) {
        float tot = 0.f;
#pragma unroll
        for (int q = 0; q < NWARP; ++q) tot += pp[q * NI + t];
        int gi = i0 + t;
        if (d < C) g_num[gi * C + d] = tot;
        else       g_den[gi] = tot;
    }
}

// ---------------- K4: out = num / den ----------------
__global__ void k_final(float* __restrict__ out) {
    int idx = blockIdx.x * blockDim.x + threadIdx.x;
    if (idx >= N * C) return;
    int i = idx / C;
    out[idx] = g_num[idx] / g_den[i];
}

// ---------------- launcher ----------------
extern "C" void kernel_launch(void* const* d_in, const int* in_sizes, int n_in,
                              void* d_out, int out_size) {
    const float* x  = (const float*)d_in[0];
    const float* ww = (const float*)d_in[1];
    if (n_in >= 2 && in_sizes[0] == 8 * C * C && in_sizes[1] == N * C) {
        const float* tmp = x; x = ww; ww = tmp;
    }
    float* out = (float*)d_out;

    cudaFuncSetAttribute(k_main, cudaFuncAttributeMaxDynamicSharedMemorySize, SMEM_BYTES);

    dim3 g1(W_COLS / 32, N / 32);
    k_gemm_w<<<g1, dim3(16, 16)>>>(x, ww);
    dim3 g2(N / 64, N / 64, 3);
    k_pqr<<<g2, dim3(16, 16)>>>();
    dim3 g3(C + 1, N / NI);
    k_main<<<g3, THREADS, SMEM_BYTES>>>();
    k_final<<<(N * C + 255) / 256, 256>>>(out);
}

// round 17
// speedup vs baseline: 1.2030x; 1.0632x over previous
#include <cuda_runtime.h>
#include <cstdint>

#define N 384
#define C 64
#define W_COLS 512
#define THREADS 256
#define NWARP 8
#define NI 64             // i-rows per CTA
#define KB 16             // k-rows per CTA
#define NKB (N / KB)      // 24 k-blocks
#define AS_LD 388         // Bs row stride (floats), conflict-free
#define Q_LD 68           // Qs row stride (floats), conflict-free

// ---------------- scratch ----------------
__device__ float g_W[N * W_COLS];          // x @ w_w^T  [384][512]
__device__ float g_P[N * N];               // tf32(exp(AB))  [i][j]
__device__ float g_QT[N * N];              // exp(CD) transposed: QT[k][i]
__device__ float g_RT[N * N];              // tf32(exp(EF)) transposed: RT[k][j]
__device__ float g_part[NKB * 65 * N];     // partial num/den: [kb][d][i]

__device__ __forceinline__ float to_tf32(float x) {
    float r;
    asm("cvt.rna.tf32.f32 %0, %1;" : "=f"(r) : "f"(x));
    return r;
}
__device__ __forceinline__ void cp16(uint32_t dst, const void* src) {
    asm volatile("cp.async.cg.shared.global [%0], [%1], 16;" :: "r"(dst), "l"(src));
}

// ---------------- K1: W = x @ w_w^T, smem-tiled 32x32 ----------------
__global__ void k_gemm_w(const float* __restrict__ x, const float* __restrict__ ww) {
    __shared__ float xs[32][67], ws[32][67];
    int o0 = blockIdx.x * 32, n0 = blockIdx.y * 32;
    int tx = threadIdx.x, ty = threadIdx.y;
    int t = ty * 16 + tx;
    for (int q = t; q < 32 * 64; q += 256) {
        int rr = q >> 6, cc = q & 63;
        xs[rr][cc] = x[(n0 + rr) * C + cc];
        ws[rr][cc] = ww[(o0 + rr) * C + cc];
    }
    __syncthreads();
    float s00 = 0.f, s01 = 0.f, s10 = 0.f, s11 = 0.f;
#pragma unroll
    for (int c = 0; c < 64; ++c) {
        float u0 = xs[2 * ty][c], u1 = xs[2 * ty + 1][c];
        float v0 = ws[2 * tx][c], v1 = ws[2 * tx + 1][c];
        s00 += u0 * v0; s01 += u0 * v1;
        s10 += u1 * v0; s11 += u1 * v1;
    }
    int n = n0 + 2 * ty, o = o0 + 2 * tx;
    g_W[n * W_COLS + o] = s00;       g_W[n * W_COLS + o + 1] = s01;
    g_W[(n + 1) * W_COLS + o] = s10; g_W[(n + 1) * W_COLS + o + 1] = s11;
}

// ---------------- K2: fused scores + exp (+transposes), 32x32 tiles ----------------
// No max-shift: scores are O(1) (w scaled 0.05); any per-matrix shift cancels in num/den.
// P and RT stored tf32-rounded (MMA operands); Q stays fp32.
__global__ void k_pqr(int z_base) {
    __shared__ float us[32][67], vs[32][67];
    int z = z_base + blockIdx.z;
    int r0 = blockIdx.y * 32, c0 = blockIdx.x * 32;
    int tx = threadIdx.x, ty = threadIdx.y;
    int t = ty * 16 + tx;
    int up = (z == 0) ? 0 : (z == 1) ? 3 : 5;
    int vp = (z == 0) ? 1 : (z == 1) ? 2 : 4;
    for (int q = t; q < 32 * 64; q += 256) {
        int rr = q >> 6, cc = q & 63;
        us[rr][cc] = g_W[(r0 + rr) * W_COLS + up * C + cc];
        vs[rr][cc] = g_W[(c0 + rr) * W_COLS + vp * C + cc];
    }
    __syncthreads();
    float s00 = 0.f, s01 = 0.f, s10 = 0.f, s11 = 0.f;
#pragma unroll
    for (int c = 0; c < 64; ++c) {
        float u0 = us[2 * ty][c], u1 = us[2 * ty + 1][c];
        float v0 = vs[2 * tx][c], v1 = vs[2 * tx + 1][c];
        s00 += u0 * v0; s01 += u0 * v1;
        s10 += u1 * v0; s11 += u1 * v1;
    }
    s00 = __expf(s00 * 0.125f);
    s01 = __expf(s01 * 0.125f);
    s10 = __expf(s10 * 0.125f);
    s11 = __expf(s11 * 0.125f);
    int row = r0 + 2 * ty, col = c0 + 2 * tx;
    if (z == 0) {
        g_P[row * N + col] = to_tf32(s00);       g_P[row * N + col + 1] = to_tf32(s01);
        g_P[(row + 1) * N + col] = to_tf32(s10); g_P[(row + 1) * N + col + 1] = to_tf32(s11);
    } else if (z == 1) {
        g_QT[row * N + col] = s00;       g_QT[row * N + col + 1] = s01;
        g_QT[(row + 1) * N + col] = s10; g_QT[(row + 1) * N + col + 1] = s11;
    } else {
        g_RT[row * N + col] = to_tf32(s00);       g_RT[row * N + col + 1] = to_tf32(s01);
        g_RT[(row + 1) * N + col] = to_tf32(s10); g_RT[(row + 1) * N + col + 1] = to_tf32(s11);
    }
}

// ---------------- K3: inverted-loop tf32 HMMA contraction ----------------
// grid = (24, 6): blockIdx.x = k-block (16 k), blockIdx.y = i-tile (64 i).
// B and Q staged ONCE; d-loop runs from registers. A = tf32(P) is d-invariant;
// v1_d folded into B fragments (diag(v1)·R), v2_d into the fold.
__device__ __forceinline__ void mma_tf32(float* c, const uint32_t* a, const uint32_t* b) {
    asm("mma.sync.aligned.m16n8k8.row.col.f32.tf32.tf32.f32 "
        "{%0,%1,%2,%3}, {%4,%5,%6,%7}, {%8,%9}, {%0,%1,%2,%3};"
        : "+f"(c[0]), "+f"(c[1]), "+f"(c[2]), "+f"(c[3])
        : "r"(a[0]), "r"(a[1]), "r"(a[2]), "r"(a[3]), "r"(b[0]), "r"(b[1]));
}

__global__ __launch_bounds__(THREADS, 1) void k_main() {
    __shared__ float Bs[KB * AS_LD];   // tf32 RT rows k0..k0+15, all j
    __shared__ float Qs[KB * Q_LD];    // QT rows k0..k0+15, cols i0..i0+63
    __shared__ float pp[NWARP * NI];

    int kb = blockIdx.x;
    int k0 = kb * KB;
    int i0 = blockIdx.y * NI;
    int t = threadIdx.x;
    int w = t >> 5, lane = t & 31;
    int g = lane >> 2, tg = lane & 3;
    int j0w = w * 48;

    uint32_t bsb = (uint32_t)__cvta_generic_to_shared(Bs);
    uint32_t qsb = (uint32_t)__cvta_generic_to_shared(Qs);

    // One-time staging: B (16 x 384) + Q (16 x 64)
    for (int q = t; q < KB * (N / 4); q += THREADS) {
        int r = q / (N / 4), u = q - r * (N / 4);
        cp16(bsb + (uint32_t)(r * AS_LD + u * 4) * 4u, &g_RT[(k0 + r) * N + u * 4]);
    }
    for (int q = t; q < KB * (NI / 4); q += THREADS) {
        int r = q >> 4, u = q & 15;
        cp16(qsb + (uint32_t)(r * Q_LD + u * 4) * 4u, &g_QT[(k0 + r) * N + i0 + u * 4]);
    }
    asm volatile("cp.async.commit_group;" ::: "memory");

    // A fragments: tf32(P) — d-invariant, built from gmem while staging lands
    uint32_t a[4][6][4];
#pragma unroll
    for (int mt = 0; mt < 4; ++mt)
#pragma unroll
        for (int js = 0; js < 6; ++js) {
            int i = i0 + mt * 16 + g;
            int j = j0w + js * 8 + tg;
            a[mt][js][0] = __float_as_uint(g_P[i * N + j]);
            a[mt][js][1] = __float_as_uint(g_P[(i + 8) * N + j]);
            a[mt][js][2] = __float_as_uint(g_P[i * N + j + 4]);
            a[mt][js][3] = __float_as_uint(g_P[(i + 8) * N + j + 4]);
        }

    asm volatile("cp.async.wait_group 0;" ::: "memory");
    __syncthreads();

    // Raw B fragments held in registers for the whole d-loop
    float braw[6][2][2];
#pragma unroll
    for (int js = 0; js < 6; ++js)
#pragma unroll
        for (int nt = 0; nt < 2; ++nt) {
            const float* bp = Bs + (nt * 8 + g) * AS_LD + j0w + js * 8 + tg;
            braw[js][nt][0] = bp[0];
            braw[js][nt][1] = bp[4];
        }

    for (int d = 0; d < C + 1; ++d) {
        // v1 (12 j-values) and v2 (4 k-values) for this d; d==64 => ones
        float v1v[6][2], v2v[2][2];
        if (d < C) {
#pragma unroll
            for (int js = 0; js < 6; ++js) {
                int j = j0w + js * 8 + tg;
                v1v[js][0] = g_W[j * W_COLS + 6 * C + d];
                v1v[js][1] = g_W[(j + 4) * W_COLS + 6 * C + d];
            }
#pragma unroll
            for (int nt = 0; nt < 2; ++nt) {
                int k = k0 + nt * 8 + 2 * tg;
                v2v[nt][0] = g_W[k * W_COLS + 7 * C + d];
                v2v[nt][1] = g_W[(k + 1) * W_COLS + 7 * C + d];
            }
        } else {
#pragma unroll
            for (int js = 0; js < 6; ++js) { v1v[js][0] = 1.f; v1v[js][1] = 1.f; }
#pragma unroll
            for (int nt = 0; nt < 2; ++nt) { v2v[nt][0] = 1.f; v2v[nt][1] = 1.f; }
        }

        float acc[4][2][4];
#pragma unroll
        for (int mt = 0; mt < 4; ++mt)
#pragma unroll
            for (int nt = 0; nt < 2; ++nt)
#pragma unroll
                for (int r = 0; r < 4; ++r) acc[mt][nt][r] = 0.f;

#pragma unroll
        for (int js = 0; js < 6; ++js) {
            uint32_t bd[2][2];
#pragma unroll
            for (int nt = 0; nt < 2; ++nt) {
                bd[nt][0] = __float_as_uint(to_tf32(braw[js][nt][0] * v1v[js][0]));
                bd[nt][1] = __float_as_uint(to_tf32(braw[js][nt][1] * v1v[js][1]));
            }
#pragma unroll
            for (int mt = 0; mt < 4; ++mt)
#pragma unroll
                for (int nt = 0; nt < 2; ++nt)
                    mma_tf32(acc[mt][nt], a[mt][js], bd[nt]);
        }

        // Fold: numacc[i] += G[i,k] * Q[k,i] * v2[k]
        float numacc[8];
#pragma unroll
        for (int s = 0; s < 8; ++s) numacc[s] = 0.f;
#pragma unroll
        for (int nt = 0; nt < 2; ++nt) {
            int kk0 = nt * 8 + 2 * tg;
#pragma unroll
            for (int mt = 0; mt < 4; ++mt)
#pragma unroll
                for (int r = 0; r < 4; ++r) {
                    int kk = kk0 + (r & 1);
                    int iloc = mt * 16 + ((r >> 1) << 3) + g;
                    numacc[mt * 2 + (r >> 1)] +=
                        acc[mt][nt][r] * Qs[kk * Q_LD + iloc] * v2v[nt][r & 1];
                }
        }

        // Quad reduce (tg), cross-warp reduce via smem, store partial
#pragma unroll
        for (int s = 0; s < 8; ++s) {
            float v = numacc[s];
            v += __shfl_xor_sync(0xffffffffu, v, 1);
            v += __shfl_xor_sync(0xffffffffu, v, 2);
            if (tg == 0) {
                int iloc = (s >> 1) * 16 + (s & 1) * 8 + g;
                pp[w * NI + iloc] = v;
            }
        }
        __syncthreads();
        if (t < NI) {
            float tot = 0.f;
#pragma unroll
            for (int q = 0; q < NWARP; ++q) tot += pp[q * NI + t];
            g_part[(kb * 65 + d) * N + i0 + t] = tot;   // coalesced
        }
        __syncthreads();   // pp reuse for next d
    }
}

// ---------------- K4: out = (sum_kb num) / (sum_kb den) ----------------
__global__ void k_final(float* __restrict__ out) {
    int tid = blockIdx.x * blockDim.x + threadIdx.x;
    if (tid >= N * C) return;
    int i = tid % N;            // i fastest -> coalesced partial reads
    int c = tid / N;
    float num = 0.f, den = 0.f;
#pragma unroll 4
    for (int kb = 0; kb < NKB; ++kb) {
        num += g_part[(kb * 65 + c) * N + i];
        den += g_part[(kb * 65 + 64) * N + i];
    }
    out[i * C + c] = num / den;
}

// ---------------- launcher ----------------
extern "C" void kernel_launch(void* const* d_in, const int* in_sizes, int n_in,
                              void* d_out, int out_size) {
    const float* x  = (const float*)d_in[0];
    const float* ww = (const float*)d_in[1];
    if (n_in >= 2 && in_sizes[0] == 8 * C * C && in_sizes[1] == N * C) {
        const float* tmp = x; x = ww; ww = tmp;
    }
    float* out = (float*)d_out;

    dim3 g1(W_COLS / 32, N / 32);
    k_gemm_w<<<g1, dim3(16, 16)>>>(x, ww);
    dim3 g2a(N / 32, N / 32, 2);
    k_pqr<<<g2a, dim3(16, 16)>>>(0);          // launch #2: P, QT
    dim3 g2b(N / 32, N / 32, 1);
    k_pqr<<<g2b, dim3(16, 16)>>>(2);          // launch #3: RT
    dim3 g3(NKB, N / NI);
    k_main<<<g3, THREADS>>>();                // launch #4 (ncu capture slot)
    k_final<<<(N * C + 255) / 256, 256>>>(out);
}